// round 15
// baseline (speedup 1.0000x reference)
#include <cuda_runtime.h>
#include <cuda_fp16.h>
#include <cstdint>
#include <limits.h>

// ---------------- problem constants ----------------
#define BATCH   8
#define CDIM    64
#define GDIM    65536
#define NLAYER  4
#define SLOPE   0.1f

#define TPB     128
#define CTAS_PER_SM 5
#define GRID    (148 * CTAS_PER_SM)         // 740
#define WARPS_PER_CTA (TPB / 32)
#define NWARPS  (GRID * WARPS_PER_CTA)      // 2960
#define WARPS_PER_BATCH (NWARPS / BATCH)    // 370
#define TILES_PER_BATCH (GDIM / 32)         // 2048 tiles of 32 columns

// smem layout (dynamic)
#define SMB_BYTES   (4 * 4 * 4 * 32 * 16)   // B fragment pairs: 32768
#define SMBIAS_OFF  SMB_BYTES               // f16x2 bias pairs: 8b*64 uint2 = 8192
#define SM_TOTAL    (SMBIAS_OFF + 8192)

#define HALF2_01    0x2E662E66u             // f16x2 {0.1, 0.1}
#define HALF2_NINF  0xFC00FC00u             // f16x2 {-inf, -inf}

// ---------------- helpers ----------------
__device__ __forceinline__ uint32_t pack_h2(float a, float b) {
    uint32_t p;
    asm("cvt.rn.f16x2.f32 %0, %1, %2;" : "=r"(p) : "f"(b), "f"(a));
    return p;
}

// f16-accumulator MMA: first step takes C = broadcast bias pair
#define MMA_H_INIT(d0, d1, a0, a1, a2, a3, b0, b1, c) \
    asm volatile("mma.sync.aligned.m16n8k16.row.col.f16.f16.f16.f16 " \
        "{%0,%1}, {%2,%3,%4,%5}, {%6,%7}, {%8,%9};" \
        : "=r"(d0), "=r"(d1) \
        : "r"(a0), "r"(a1), "r"(a2), "r"(a3), "r"(b0), "r"(b1), "r"(c), "r"(c))

#define MMA_H_ACC(d0, d1, a0, a1, a2, a3, b0, b1) \
    asm volatile("mma.sync.aligned.m16n8k16.row.col.f16.f16.f16.f16 " \
        "{%0,%1}, {%2,%3,%4,%5}, {%6,%7}, {%0,%1};" \
        : "+r"(d0), "+r"(d1) \
        : "r"(a0), "r"(a1), "r"(a2), "r"(a3), "r"(b0), "r"(b1))

// leaky relu on packed f16x2 (in place)
#define LRELU2(x) do { \
    uint32_t _m; \
    asm("mul.f16x2 %0, %1, %2;" : "=r"(_m) : "r"(x), "r"(HALF2_01)); \
    asm("max.f16x2 %0, %1, %2;" : "=r"(x) : "r"(x), "r"(_m)); \
} while (0)

#define HMAX2(d, a, b) \
    asm("max.f16x2 %0, %1, %2;" : "=r"(d) : "r"(a), "r"(b))

// monotone uint key; 0 == -inf sentinel (matches zero-init of __device__ globals)
__device__ __forceinline__ unsigned f2ukey(float f) {
    int b = __float_as_int(f);
    b = (b >= 0) ? b : (b ^ 0x7fffffff);
    return (unsigned)b ^ 0x80000000u;
}
__device__ __forceinline__ float ukey2f(unsigned u) {
    int k = (int)(u ^ 0x80000000u);
    return __int_as_float(k >= 0 ? k : (k ^ 0x7fffffff));
}
__device__ __forceinline__ float lrelu(float a) { return fmaxf(a, SLOPE * a); }

// ---------------- device globals (zero-init .bss; mlp restores to 0) --------
__device__ float    g_bias[NLAYER][BATCH][64];
__device__ unsigned g_maxkey[BATCH * 64];
__device__ int      g_done;

// ---------------- kernel 0: bias chain (parallel, one block per batch) ------
__global__ void setup_kernel(const float* __restrict__ feat,
                             const float* __restrict__ W0,
                             const float* __restrict__ W1,
                             const float* __restrict__ W2,
                             const float* __restrict__ W3) {
    const float* Ws[NLAYER] = {W0, W1, W2, W3};
    const int b = blockIdx.x;
    const int o = threadIdx.x;
    __shared__ float sx0[64];
    __shared__ float sy[64];

    sx0[o] = feat[(size_t)b * CDIM * GDIM + (size_t)o * GDIM];  // g = 0
    __syncthreads();
    #pragma unroll 1
    for (int l = 0; l < NLAYER; l++) {
        const float* wr = Ws[l] + o * 128;
        float da = 0.f, db = 0.f;
        #pragma unroll
        for (int c = 0; c < 64; c++) {
            float xv = sx0[c];
            da = fmaf(wr[c], xv, da);
            db = fmaf(wr[64 + c], xv, db);
        }
        g_bias[l][b][o] = -db;
        sy[o] = lrelu(da);
        __syncthreads();
        sx0[o] = sy[o];
        __syncthreads();
    }
}

// ---- layer macro: all-j-live f16 D; D regs ARE next layer's A regs ----
// S0/S1, T0/T1: uint32_t[16] (two m16 halves). bias C on sb=0 step.
#define LAYER_H(lc, S0, S1, T0, T1) do {                                      \
    const uint4* Bl = sB + (lc) * (4 * 4 * 32) + lane;                        \
    const uint2* bp = sbias_b + (lc) * 16 + t;                                \
    _Pragma("unroll")                                                         \
    for (int jp = 0; jp < 4; jp++) {                                          \
        uint4 bf = Bl[jp * 32];                                               \
        uint2 bv = bp[jp * 4];                                                \
        MMA_H_INIT(T0[4*jp+0], T0[4*jp+1], S0[0], S0[1], S0[2], S0[3], bf.x, bf.y, bv.x); \
        MMA_H_INIT(T1[4*jp+0], T1[4*jp+1], S1[0], S1[1], S1[2], S1[3], bf.x, bf.y, bv.x); \
        MMA_H_INIT(T0[4*jp+2], T0[4*jp+3], S0[0], S0[1], S0[2], S0[3], bf.z, bf.w, bv.y); \
        MMA_H_INIT(T1[4*jp+2], T1[4*jp+3], S1[0], S1[1], S1[2], S1[3], bf.z, bf.w, bv.y); \
    }                                                                         \
    _Pragma("unroll")                                                         \
    for (int sb = 1; sb < 4; sb++) {                                          \
        _Pragma("unroll")                                                     \
        for (int jp = 0; jp < 4; jp++) {                                      \
            uint4 bf = Bl[(sb * 4 + jp) * 32];                                \
            MMA_H_ACC(T0[4*jp+0], T0[4*jp+1], S0[4*sb+0], S0[4*sb+1], S0[4*sb+2], S0[4*sb+3], bf.x, bf.y); \
            MMA_H_ACC(T1[4*jp+0], T1[4*jp+1], S1[4*sb+0], S1[4*sb+1], S1[4*sb+2], S1[4*sb+3], bf.x, bf.y); \
            MMA_H_ACC(T0[4*jp+2], T0[4*jp+3], S0[4*sb+0], S0[4*sb+1], S0[4*sb+2], S0[4*sb+3], bf.z, bf.w); \
            MMA_H_ACC(T1[4*jp+2], T1[4*jp+3], S1[4*sb+0], S1[4*sb+1], S1[4*sb+2], S1[4*sb+3], bf.z, bf.w); \
        }                                                                     \
    }                                                                         \
    _Pragma("unroll")                                                         \
    for (int i = 0; i < 16; i++) { LRELU2(T0[i]); LRELU2(T1[i]); }            \
} while (0)

// ---------------- kernel 1: persistent fp16-accumulator MLP -----------------
__global__ void __launch_bounds__(TPB, CTAS_PER_SM)
mlp_kernel(const float* __restrict__ feat,
           const float* __restrict__ W0, const float* __restrict__ W1,
           const float* __restrict__ W2, const float* __restrict__ W3,
           float* __restrict__ out) {
    extern __shared__ char smem[];
    uint4* sB      = (uint4*)smem;                  // [l][sb:4][jp:4][lane:32]
    uint2* sbias16 = (uint2*)(smem + SMBIAS_OFF);   // [b][l][jp][t] f16x2 pairs

    const int tid  = threadIdx.x;
    const int wid  = tid >> 5;
    const int lane = tid & 31;
    const int g    = lane >> 2;
    const int t    = lane & 3;

    // ---- prologue: pack B fragment PAIRS (Weff -> fp16) + bias f16x2 pack ----
    {
        const float* Ws[NLAYER] = {W0, W1, W2, W3};
        for (int idx = tid; idx < 4 * 4 * 4 * 32; idx += TPB) {
            int ln = idx & 31, jp = (idx >> 5) & 3, sb = (idx >> 7) & 3, l = idx >> 9;
            int gg = ln >> 2, tt = ln & 3;
            int cb = 16 * sb + 2 * tt;
            uint32_t v[4];
            #pragma unroll
            for (int h = 0; h < 2; h++) {
                int o = 8 * (2 * jp + h) + gg;
                const float* W = Ws[l] + o * 128;
                float v0 = W[cb]     + W[64 + cb];
                float v1 = W[cb + 1] + W[64 + cb + 1];
                float v8 = W[cb + 8] + W[64 + cb + 8];
                float v9 = W[cb + 9] + W[64 + cb + 9];
                v[2 * h]     = pack_h2(v0, v1);
                v[2 * h + 1] = pack_h2(v8, v9);
            }
            sB[idx] = make_uint4(v[0], v[1], v[2], v[3]);
        }
        // bias pairs: sbias16[b*64 + l*16 + jp*4 + t] = {bias2(j=2jp), bias2(j=2jp+1)}
        for (int idx = tid; idx < BATCH * 64; idx += TPB) {
            int tt = idx & 3, jp = (idx >> 2) & 3, l = (idx >> 4) & 3, b = idx >> 6;
            const float* gb = g_bias[l][b];
            int c0 = 8 * (2 * jp) + 2 * tt;
            int c1 = 8 * (2 * jp + 1) + 2 * tt;
            sbias16[idx] = make_uint2(pack_h2(gb[c0], gb[c0 + 1]),
                                      pack_h2(gb[c1], gb[c1 + 1]));
        }
    }
    __syncthreads();

    // ---- batch-locked warp -> tile mapping ----
    const int wglobal = blockIdx.x * WARPS_PER_CTA + wid;
    const int b       = wglobal & 7;
    const int tstart  = wglobal >> 3;
    const float* fbase = feat + (size_t)b * CDIM * GDIM;
    const uint2* sbias_b = sbias16 + b * 64;

    // packed f16x2 running max per j (this lane's channels 8j+2t, 8j+2t+1)
    uint32_t Rm[8];
    #pragma unroll
    for (int j = 0; j < 8; j++) Rm[j] = HALF2_NINF;

    for (int ti = tstart; ti < TILES_PER_BATCH; ti += WARPS_PER_BATCH) {
        // ---- vectorized X load (column-permuted; max is permutation-invariant) ----
        uint32_t Ax0[16], Ax1[16], Ay0[16], Ay1[16];
        {
            const float* fp = fbase + ((uint32_t)ti << 5);
            #pragma unroll
            for (int s = 0; s < 4; s++) {
                const uint32_t c0 = 16 * s + 2 * t;
                const float4 v0 = __ldg((const float4*)(fp + (size_t)c0 * GDIM) + g);
                const float4 v1 = __ldg((const float4*)(fp + (size_t)(c0 + 1) * GDIM) + g);
                const float4 v8 = __ldg((const float4*)(fp + (size_t)(c0 + 8) * GDIM) + g);
                const float4 v9 = __ldg((const float4*)(fp + (size_t)(c0 + 9) * GDIM) + g);
                Ax0[4*s+0] = pack_h2(v0.x, v1.x);
                Ax0[4*s+1] = pack_h2(v0.y, v1.y);
                Ax0[4*s+2] = pack_h2(v8.x, v9.x);
                Ax0[4*s+3] = pack_h2(v8.y, v9.y);
                Ax1[4*s+0] = pack_h2(v0.z, v1.z);
                Ax1[4*s+1] = pack_h2(v0.w, v1.w);
                Ax1[4*s+2] = pack_h2(v8.z, v9.z);
                Ax1[4*s+3] = pack_h2(v8.w, v9.w);
            }
        }

        // ---- layers 0..2 (D regs become next A regs; ping-pong buffers) ----
        LAYER_H(0, Ax0, Ax1, Ay0, Ay1);
        LAYER_H(1, Ay0, Ay1, Ax0, Ax1);
        LAYER_H(2, Ax0, Ax1, Ay0, Ay1);

        // ---- final layer: jp-outer (8 D regs live), hmax into Rm ----
        {
            const uint4* Bl = sB + 3 * (4 * 4 * 32) + lane;
            const uint2* bp = sbias_b + 3 * 16 + t;
            #pragma unroll
            for (int jp = 0; jp < 4; jp++) {
                uint2 bv = bp[jp * 4];
                uint32_t d00, d01, d10, d11;   // j = 2jp,   halves 0/1
                uint32_t e00, e01, e10, e11;   // j = 2jp+1, halves 0/1
                {
                    uint4 bf = Bl[jp * 32];
                    MMA_H_INIT(d00, d01, Ay0[0], Ay0[1], Ay0[2], Ay0[3], bf.x, bf.y, bv.x);
                    MMA_H_INIT(d10, d11, Ay1[0], Ay1[1], Ay1[2], Ay1[3], bf.x, bf.y, bv.x);
                    MMA_H_INIT(e00, e01, Ay0[0], Ay0[1], Ay0[2], Ay0[3], bf.z, bf.w, bv.y);
                    MMA_H_INIT(e10, e11, Ay1[0], Ay1[1], Ay1[2], Ay1[3], bf.z, bf.w, bv.y);
                }
                #pragma unroll
                for (int sb = 1; sb < 4; sb++) {
                    uint4 bf = Bl[(sb * 4 + jp) * 32];
                    MMA_H_ACC(d00, d01, Ay0[4*sb+0], Ay0[4*sb+1], Ay0[4*sb+2], Ay0[4*sb+3], bf.x, bf.y);
                    MMA_H_ACC(d10, d11, Ay1[4*sb+0], Ay1[4*sb+1], Ay1[4*sb+2], Ay1[4*sb+3], bf.x, bf.y);
                    MMA_H_ACC(e00, e01, Ay0[4*sb+0], Ay0[4*sb+1], Ay0[4*sb+2], Ay0[4*sb+3], bf.z, bf.w);
                    MMA_H_ACC(e10, e11, Ay1[4*sb+0], Ay1[4*sb+1], Ay1[4*sb+2], Ay1[4*sb+3], bf.z, bf.w);
                }
                LRELU2(d00); LRELU2(d01); LRELU2(d10); LRELU2(d11);
                LRELU2(e00); LRELU2(e01); LRELU2(e10); LRELU2(e11);
                uint32_t m;
                HMAX2(m, d00, d01); HMAX2(d10, d10, d11); HMAX2(m, m, d10);
                HMAX2(Rm[2*jp], Rm[2*jp], m);
                HMAX2(m, e00, e01); HMAX2(e10, e10, e11); HMAX2(m, m, e10);
                HMAX2(Rm[2*jp+1], Rm[2*jp+1], m);
            }
        }
    }

    // ---- once-per-warp reduce (packed) + global atomics ----
    #pragma unroll
    for (int j = 0; j < 8; j++) {
        uint32_t m = Rm[j], o;
        o = __shfl_xor_sync(0xffffffffu, m, 4);  HMAX2(m, m, o);
        o = __shfl_xor_sync(0xffffffffu, m, 8);  HMAX2(m, m, o);
        o = __shfl_xor_sync(0xffffffffu, m, 16); HMAX2(m, m, o);
        if (lane < 4) {
            __half2 h = *reinterpret_cast<__half2*>(&m);
            atomicMax(&g_maxkey[b * 64 + 8 * j + 2 * t],     f2ukey(__low2float(h)));
            atomicMax(&g_maxkey[b * 64 + 8 * j + 2 * t + 1], f2ukey(__high2float(h)));
        }
    }
    __threadfence();

    // ---- last CTA writes output and restores global state to 0 ----
    __syncthreads();
    __shared__ int slast;
    if (tid == 0) slast = (atomicAdd(&g_done, 1) == GRID - 1) ? 1 : 0;
    __syncthreads();
    if (slast) {
        __threadfence();
        for (int idx = tid; idx < BATCH * 64; idx += TPB) {
            unsigned k = atomicMax(&g_maxkey[idx], 0u);   // atomic read (0 = identity)
            out[idx] = ukey2f(k);
            g_maxkey[idx] = 0u;                            // restore for next replay
        }
        __threadfence();
        if (tid == 0) g_done = 0;                          // restore counter
    }
}

// ---------------------------------------------------------------------------
extern "C" void kernel_launch(void* const* d_in, const int* in_sizes, int n_in,
                              void* d_out, int out_size) {
    const float* feat = (const float*)d_in[0];
    const float* W0   = (const float*)d_in[1];
    const float* W1   = (const float*)d_in[2];
    const float* W2   = (const float*)d_in[3];
    const float* W3   = (const float*)d_in[4];
    float* out = (float*)d_out;

    cudaFuncSetAttribute(mlp_kernel, cudaFuncAttributeMaxDynamicSharedMemorySize, SM_TOTAL);

    setup_kernel<<<BATCH, 64>>>(feat, W0, W1, W2, W3);               // 0
    mlp_kernel<<<GRID, TPB, SM_TOTAL>>>(feat, W0, W1, W2, W3, out);  // 1
}

// round 17
// speedup vs baseline: 1.1677x; 1.1677x over previous
#include <cuda_runtime.h>
#include <cuda_fp16.h>
#include <cstdint>
#include <limits.h>

// ---------------- problem constants ----------------
#define BATCH   8
#define CDIM    64
#define GDIM    65536
#define NLAYER  4
#define SLOPE   0.1f

#define TPB     256
#define CTAS_PER_SM 2
#define GRID    (148 * CTAS_PER_SM)         // 296
#define WARPS_PER_CTA (TPB / 32)
#define NWARPS  (GRID * WARPS_PER_CTA)      // 2368
#define WARPS_PER_BATCH (NWARPS / BATCH)    // 296
#define TILES_PER_BATCH (GDIM / 32)         // 2048 tiles of 32 columns

// smem layout (dynamic)
#define SMB_BYTES   (4 * 4 * 4 * 32 * 16)   // B fragment pairs: 32768
#define SMBIAS_OFF  SMB_BYTES               // f16x2 bias pairs: 8b*64 uint2 = 8192
#define SM_TOTAL    (SMBIAS_OFF + 8192)

#define HALF2_01    0x2E662E66u             // f16x2 {0.1, 0.1}
#define HALF2_NINF  0xFC00FC00u             // f16x2 {-inf, -inf}

// ---------------- helpers ----------------
__device__ __forceinline__ uint32_t pack_h2(float a, float b) {
    uint32_t p;
    asm("cvt.rn.f16x2.f32 %0, %1, %2;" : "=r"(p) : "f"(b), "f"(a));
    return p;
}

// f16-accumulator MMA: first step takes C = broadcast bias pair
#define MMA_H_INIT(d0, d1, a0, a1, a2, a3, b0, b1, c) \
    asm volatile("mma.sync.aligned.m16n8k16.row.col.f16.f16.f16.f16 " \
        "{%0,%1}, {%2,%3,%4,%5}, {%6,%7}, {%8,%9};" \
        : "=r"(d0), "=r"(d1) \
        : "r"(a0), "r"(a1), "r"(a2), "r"(a3), "r"(b0), "r"(b1), "r"(c), "r"(c))

#define MMA_H_ACC(d0, d1, a0, a1, a2, a3, b0, b1) \
    asm volatile("mma.sync.aligned.m16n8k16.row.col.f16.f16.f16.f16 " \
        "{%0,%1}, {%2,%3,%4,%5}, {%6,%7}, {%0,%1};" \
        : "+r"(d0), "+r"(d1) \
        : "r"(a0), "r"(a1), "r"(a2), "r"(a3), "r"(b0), "r"(b1))

// leaky relu on packed f16x2 (in place)
#define LRELU2(x) do { \
    uint32_t _m; \
    asm("mul.f16x2 %0, %1, %2;" : "=r"(_m) : "r"(x), "r"(HALF2_01)); \
    asm("max.f16x2 %0, %1, %2;" : "=r"(x) : "r"(x), "r"(_m)); \
} while (0)

#define HMAX2(d, a, b) \
    asm("max.f16x2 %0, %1, %2;" : "=r"(d) : "r"(a), "r"(b))

// monotone uint key; 0 == -inf sentinel (matches zero-init of __device__ globals)
__device__ __forceinline__ unsigned f2ukey(float f) {
    int b = __float_as_int(f);
    b = (b >= 0) ? b : (b ^ 0x7fffffff);
    return (unsigned)b ^ 0x80000000u;
}
__device__ __forceinline__ float ukey2f(unsigned u) {
    int k = (int)(u ^ 0x80000000u);
    return __int_as_float(k >= 0 ? k : (k ^ 0x7fffffff));
}
__device__ __forceinline__ float lrelu(float a) { return fmaxf(a, SLOPE * a); }

// ---------------- device globals (zero-init .bss; mlp restores to 0) --------
__device__ float    g_bias[NLAYER][BATCH][64];
__device__ unsigned g_maxkey[BATCH * 64];
__device__ int      g_done;

// ---------------- kernel 0: bias chain (parallel, one block per batch) ------
__global__ void setup_kernel(const float* __restrict__ feat,
                             const float* __restrict__ W0,
                             const float* __restrict__ W1,
                             const float* __restrict__ W2,
                             const float* __restrict__ W3) {
    const float* Ws[NLAYER] = {W0, W1, W2, W3};
    const int b = blockIdx.x;
    const int o = threadIdx.x;
    __shared__ float sx0[64];
    __shared__ float sy[64];

    sx0[o] = feat[(size_t)b * CDIM * GDIM + (size_t)o * GDIM];  // g = 0
    __syncthreads();
    #pragma unroll 1
    for (int l = 0; l < NLAYER; l++) {
        const float* wr = Ws[l] + o * 128;
        float da = 0.f, db = 0.f;
        #pragma unroll
        for (int c = 0; c < 64; c++) {
            float xv = sx0[c];
            da = fmaf(wr[c], xv, da);
            db = fmaf(wr[64 + c], xv, db);
        }
        g_bias[l][b][o] = -db;
        sy[o] = lrelu(da);
        __syncthreads();
        sx0[o] = sy[o];
        __syncthreads();
    }
}

// ---- layer macro: all-j-live f16 D; D regs ARE next layer's A regs ----
// S0/S1, T0/T1: uint32_t[16] (two m16 halves). bias C on sb=0 step.
#define LAYER_H(lc, S0, S1, T0, T1) do {                                      \
    const uint4* Bl = sB + (lc) * (4 * 4 * 32) + lane;                        \
    const uint2* bp = sbias_b + (lc) * 16 + t;                                \
    _Pragma("unroll")                                                         \
    for (int jp = 0; jp < 4; jp++) {                                          \
        uint4 bf = Bl[jp * 32];                                               \
        uint2 bv = bp[jp * 4];                                                \
        MMA_H_INIT(T0[4*jp+0], T0[4*jp+1], S0[0], S0[1], S0[2], S0[3], bf.x, bf.y, bv.x); \
        MMA_H_INIT(T1[4*jp+0], T1[4*jp+1], S1[0], S1[1], S1[2], S1[3], bf.x, bf.y, bv.x); \
        MMA_H_INIT(T0[4*jp+2], T0[4*jp+3], S0[0], S0[1], S0[2], S0[3], bf.z, bf.w, bv.y); \
        MMA_H_INIT(T1[4*jp+2], T1[4*jp+3], S1[0], S1[1], S1[2], S1[3], bf.z, bf.w, bv.y); \
    }                                                                         \
    _Pragma("unroll")                                                         \
    for (int sb = 1; sb < 4; sb++) {                                          \
        _Pragma("unroll")                                                     \
        for (int jp = 0; jp < 4; jp++) {                                      \
            uint4 bf = Bl[(sb * 4 + jp) * 32];                                \
            MMA_H_ACC(T0[4*jp+0], T0[4*jp+1], S0[4*sb+0], S0[4*sb+1], S0[4*sb+2], S0[4*sb+3], bf.x, bf.y); \
            MMA_H_ACC(T1[4*jp+0], T1[4*jp+1], S1[4*sb+0], S1[4*sb+1], S1[4*sb+2], S1[4*sb+3], bf.x, bf.y); \
            MMA_H_ACC(T0[4*jp+2], T0[4*jp+3], S0[4*sb+0], S0[4*sb+1], S0[4*sb+2], S0[4*sb+3], bf.z, bf.w); \
            MMA_H_ACC(T1[4*jp+2], T1[4*jp+3], S1[4*sb+0], S1[4*sb+1], S1[4*sb+2], S1[4*sb+3], bf.z, bf.w); \
        }                                                                     \
    }                                                                         \
    _Pragma("unroll")                                                         \
    for (int i = 0; i < 16; i++) { LRELU2(T0[i]); LRELU2(T1[i]); }            \
} while (0)

// ---------------- kernel 1: persistent fp16-accumulator MLP -----------------
// R11 geometry (296 x 256, 16 warps/SM, balanced 6.92 tiles/warp) with the
// fp16 engine (no epilogue repack, bias via MMA C operand, packed max).
__global__ void __launch_bounds__(TPB, CTAS_PER_SM)
mlp_kernel(const float* __restrict__ feat,
           const float* __restrict__ W0, const float* __restrict__ W1,
           const float* __restrict__ W2, const float* __restrict__ W3,
           float* __restrict__ out) {
    extern __shared__ char smem[];
    uint4* sB      = (uint4*)smem;                  // [l][sb:4][jp:4][lane:32]
    uint2* sbias16 = (uint2*)(smem + SMBIAS_OFF);   // [b][l][jp][t] f16x2 pairs

    const int tid  = threadIdx.x;
    const int wid  = tid >> 5;
    const int lane = tid & 31;
    const int g    = lane >> 2;
    const int t    = lane & 3;

    // ---- prologue: pack B fragment PAIRS (Weff -> fp16) + bias f16x2 pack ----
    {
        const float* Ws[NLAYER] = {W0, W1, W2, W3};
        for (int idx = tid; idx < 4 * 4 * 4 * 32; idx += TPB) {
            int ln = idx & 31, jp = (idx >> 5) & 3, sb = (idx >> 7) & 3, l = idx >> 9;
            int gg = ln >> 2, tt = ln & 3;
            int cb = 16 * sb + 2 * tt;
            uint32_t v[4];
            #pragma unroll
            for (int h = 0; h < 2; h++) {
                int o = 8 * (2 * jp + h) + gg;
                const float* W = Ws[l] + o * 128;
                float v0 = W[cb]     + W[64 + cb];
                float v1 = W[cb + 1] + W[64 + cb + 1];
                float v8 = W[cb + 8] + W[64 + cb + 8];
                float v9 = W[cb + 9] + W[64 + cb + 9];
                v[2 * h]     = pack_h2(v0, v1);
                v[2 * h + 1] = pack_h2(v8, v9);
            }
            sB[idx] = make_uint4(v[0], v[1], v[2], v[3]);
        }
        // bias pairs: sbias16[b*64 + l*16 + jp*4 + t] = {bias2(j=2jp), bias2(j=2jp+1)}
        for (int idx = tid; idx < BATCH * 64; idx += TPB) {
            int tt = idx & 3, jp = (idx >> 2) & 3, l = (idx >> 4) & 3, b = idx >> 6;
            const float* gb = g_bias[l][b];
            int c0 = 8 * (2 * jp) + 2 * tt;
            int c1 = 8 * (2 * jp + 1) + 2 * tt;
            sbias16[idx] = make_uint2(pack_h2(gb[c0], gb[c0 + 1]),
                                      pack_h2(gb[c1], gb[c1 + 1]));
        }
    }
    __syncthreads();

    // ---- batch-locked warp -> tile mapping (balanced: 2368 warps) ----
    const int wglobal = blockIdx.x * WARPS_PER_CTA + wid;
    const int b       = wglobal & 7;
    const int tstart  = wglobal >> 3;
    const float* fbase = feat + (size_t)b * CDIM * GDIM;
    const uint2* sbias_b = sbias16 + b * 64;

    // packed f16x2 running max per j (this lane's channels 8j+2t, 8j+2t+1)
    uint32_t Rm[8];
    #pragma unroll
    for (int j = 0; j < 8; j++) Rm[j] = HALF2_NINF;

    for (int ti = tstart; ti < TILES_PER_BATCH; ti += WARPS_PER_BATCH) {
        // ---- vectorized X load (column-permuted; max is permutation-invariant) ----
        uint32_t Ax0[16], Ax1[16], Ay0[16], Ay1[16];
        {
            const float* fp = fbase + ((uint32_t)ti << 5);
            #pragma unroll
            for (int s = 0; s < 4; s++) {
                const uint32_t c0 = 16 * s + 2 * t;
                const float4 v0 = __ldg((const float4*)(fp + (size_t)c0 * GDIM) + g);
                const float4 v1 = __ldg((const float4*)(fp + (size_t)(c0 + 1) * GDIM) + g);
                const float4 v8 = __ldg((const float4*)(fp + (size_t)(c0 + 8) * GDIM) + g);
                const float4 v9 = __ldg((const float4*)(fp + (size_t)(c0 + 9) * GDIM) + g);
                Ax0[4*s+0] = pack_h2(v0.x, v1.x);
                Ax0[4*s+1] = pack_h2(v0.y, v1.y);
                Ax0[4*s+2] = pack_h2(v8.x, v9.x);
                Ax0[4*s+3] = pack_h2(v8.y, v9.y);
                Ax1[4*s+0] = pack_h2(v0.z, v1.z);
                Ax1[4*s+1] = pack_h2(v0.w, v1.w);
                Ax1[4*s+2] = pack_h2(v8.z, v9.z);
                Ax1[4*s+3] = pack_h2(v8.w, v9.w);
            }
        }

        // ---- layers 0..2 (D regs become next A regs; ping-pong buffers) ----
        LAYER_H(0, Ax0, Ax1, Ay0, Ay1);
        LAYER_H(1, Ay0, Ay1, Ax0, Ax1);
        LAYER_H(2, Ax0, Ax1, Ay0, Ay1);

        // ---- final layer: jp-outer (8 D regs live), hmax into Rm ----
        {
            const uint4* Bl = sB + 3 * (4 * 4 * 32) + lane;
            const uint2* bp = sbias_b + 3 * 16 + t;
            #pragma unroll
            for (int jp = 0; jp < 4; jp++) {
                uint2 bv = bp[jp * 4];
                uint32_t d00, d01, d10, d11;   // j = 2jp,   halves 0/1
                uint32_t e00, e01, e10, e11;   // j = 2jp+1, halves 0/1
                {
                    uint4 bf = Bl[jp * 32];
                    MMA_H_INIT(d00, d01, Ay0[0], Ay0[1], Ay0[2], Ay0[3], bf.x, bf.y, bv.x);
                    MMA_H_INIT(d10, d11, Ay1[0], Ay1[1], Ay1[2], Ay1[3], bf.x, bf.y, bv.x);
                    MMA_H_INIT(e00, e01, Ay0[0], Ay0[1], Ay0[2], Ay0[3], bf.z, bf.w, bv.y);
                    MMA_H_INIT(e10, e11, Ay1[0], Ay1[1], Ay1[2], Ay1[3], bf.z, bf.w, bv.y);
                }
                #pragma unroll
                for (int sb = 1; sb < 4; sb++) {
                    uint4 bf = Bl[(sb * 4 + jp) * 32];
                    MMA_H_ACC(d00, d01, Ay0[4*sb+0], Ay0[4*sb+1], Ay0[4*sb+2], Ay0[4*sb+3], bf.x, bf.y);
                    MMA_H_ACC(d10, d11, Ay1[4*sb+0], Ay1[4*sb+1], Ay1[4*sb+2], Ay1[4*sb+3], bf.x, bf.y);
                    MMA_H_ACC(e00, e01, Ay0[4*sb+0], Ay0[4*sb+1], Ay0[4*sb+2], Ay0[4*sb+3], bf.z, bf.w);
                    MMA_H_ACC(e10, e11, Ay1[4*sb+0], Ay1[4*sb+1], Ay1[4*sb+2], Ay1[4*sb+3], bf.z, bf.w);
                }
                LRELU2(d00); LRELU2(d01); LRELU2(d10); LRELU2(d11);
                LRELU2(e00); LRELU2(e01); LRELU2(e10); LRELU2(e11);
                uint32_t m;
                HMAX2(m, d00, d01); HMAX2(d10, d10, d11); HMAX2(m, m, d10);
                HMAX2(Rm[2*jp], Rm[2*jp], m);
                HMAX2(m, e00, e01); HMAX2(e10, e10, e11); HMAX2(m, m, e10);
                HMAX2(Rm[2*jp+1], Rm[2*jp+1], m);
            }
        }
    }

    // ---- once-per-warp reduce (packed) + global atomics ----
    #pragma unroll
    for (int j = 0; j < 8; j++) {
        uint32_t m = Rm[j], o;
        o = __shfl_xor_sync(0xffffffffu, m, 4);  HMAX2(m, m, o);
        o = __shfl_xor_sync(0xffffffffu, m, 8);  HMAX2(m, m, o);
        o = __shfl_xor_sync(0xffffffffu, m, 16); HMAX2(m, m, o);
        if (lane < 4) {
            __half2 h = *reinterpret_cast<__half2*>(&m);
            atomicMax(&g_maxkey[b * 64 + 8 * j + 2 * t],     f2ukey(__low2float(h)));
            atomicMax(&g_maxkey[b * 64 + 8 * j + 2 * t + 1], f2ukey(__high2float(h)));
        }
    }
    __threadfence();

    // ---- last CTA writes output and restores global state to 0 ----
    __syncthreads();
    __shared__ int slast;
    if (tid == 0) slast = (atomicAdd(&g_done, 1) == GRID - 1) ? 1 : 0;
    __syncthreads();
    if (slast) {
        __threadfence();
        for (int idx = tid; idx < BATCH * 64; idx += TPB) {
            unsigned k = atomicMax(&g_maxkey[idx], 0u);   // atomic read (0 = identity)
            out[idx] = ukey2f(k);
            g_maxkey[idx] = 0u;                            // restore for next replay
        }
        __threadfence();
        if (tid == 0) g_done = 0;                          // restore counter
    }
}

// ---------------------------------------------------------------------------
extern "C" void kernel_launch(void* const* d_in, const int* in_sizes, int n_in,
                              void* d_out, int out_size) {
    const float* feat = (const float*)d_in[0];
    const float* W0   = (const float*)d_in[1];
    const float* W1   = (const float*)d_in[2];
    const float* W2   = (const float*)d_in[3];
    const float* W3   = (const float*)d_in[4];
    float* out = (float*)d_out;

    cudaFuncSetAttribute(mlp_kernel, cudaFuncAttributeMaxDynamicSharedMemorySize, SM_TOTAL);

    setup_kernel<<<BATCH, 64>>>(feat, W0, W1, W2, W3);               // 0
    mlp_kernel<<<GRID, TPB, SM_TOTAL>>>(feat, W0, W1, W2, W3, out);  // 1
}